// round 9
// baseline (speedup 1.0000x reference)
#include <cuda_runtime.h>
#include <cuda_fp16.h>
#include <math.h>

// ---------------------------------------------------------------------------
// TOF PET forward projection.
//  Pass 1 (fused prep): smem-tiled (16x16, 324 blocks) build of corner-packed
//          fp16 image in row-major AND transposed layouts + event params.
//  Pass 2: 8 threads/event, strength-reduced loop, f32x2 packed increments.
// ---------------------------------------------------------------------------

#define PAD_W   384            // stride (entries) for BOTH layouts
#define PADX    40
#define PADY    40
#define NSAMP   256
#define INV_NSAMP (1.0f / 256.0f)
#define ZCUT    3.6f           // Gaussian truncation: tail 2*Q(3.6) ~ 3.2e-4
#define SPLIT   8              // threads per event
#define EMAX    160000
#define NTILE   18             // 18x18 tiles of 16 cover ix,iy in [-1, 286]

// 8-byte corner pack for entry[v][u]:
//   lo = (c00, c10) = (val(u,v),   val(u,v+1))
//   hi = (c01, c11) = (val(u+1,v), val(u+1,v+1))
struct __align__(8) h4 { __half2 lo, hi; };

// Zero-initialized; pad borders stay zero (outside-image masking).
__device__ h4 g_padh [PAD_W * PAD_W];   // (u,v) = (x,y)
__device__ h4 g_padhT[PAD_W * PAD_W];   // (u,v) = (y,x)

// Per-event parameters.
__device__ float4 g_pA[EMAX];   // a0(+PADX), da, b0(+PADY), db
__device__ float4 g_pB[EMAX];   // z0, dz, scale, bits(i_lo | i_hi<<8 | steep<<31)

__global__ void prep_kernel(const float* __restrict__ img,
               const float* __restrict__ tof,
               const float* __restrict__ x1l, const float* __restrict__ y1l,
               const float* __restrict__ x1r, const float* __restrict__ y1r,
               const float* __restrict__ x2l, const float* __restrict__ y2l,
               const float* __restrict__ x2r, const float* __restrict__ y2r,
               const float* __restrict__ trp,
               const float* __restrict__ dxp, const float* __restrict__ dyp,
               const int* __restrict__ nxp, const int* __restrict__ nyp,
               int E)
{
    const int nx = *nxp;
    const int ny = *nyp;
    const int tid = threadIdx.x;
    const int blk = blockIdx.x;
    const int NTILES = NTILE * NTILE;

    if (blk < NTILES) {
        // ---- image-tile block: build BOTH layouts from one smem tile ----
        __shared__ float sm[17][18];
        const int ty = blk / NTILE;
        const int tx = blk - ty * NTILE;
        const int ixs = -1 + tx * 16;          // tile origin in image coords
        const int iys = -1 + ty * 16;

        for (int k = tid; k < 17 * 17; k += 256) {
            const int r = k / 17;
            const int c = k - r * 17;
            const int y = iys + r;
            const int x = ixs + c;
            sm[r][c] = (x >= 0 && x < nx && y >= 0 && y < ny)
                       ? img[y * nx + x] : 0.0f;
        }
        __syncthreads();

        // Row-major output: fast axis = x (coalesced 8B stores).
        {
            const int ly = tid >> 4;           // 0..15
            const int lx = tid & 15;
            h4 o;
            o.lo = __floats2half2_rn(sm[ly][lx],     sm[ly + 1][lx]);
            o.hi = __floats2half2_rn(sm[ly][lx + 1], sm[ly + 1][lx + 1]);
            g_padh[(iys + ly + PADY) * PAD_W + (ixs + lx + PADX)] = o;
        }
        // Transposed output: fast axis = y (coalesced 8B stores).
        {
            const int lx = tid >> 4;           // slow: x
            const int ly = tid & 15;           // fast: y
            h4 o;                               // (u,v) = (y,x)
            o.lo = __floats2half2_rn(sm[ly][lx],     sm[ly][lx + 1]);
            o.hi = __floats2half2_rn(sm[ly + 1][lx], sm[ly + 1][lx + 1]);
            g_padhT[(ixs + lx + PADX) * PAD_W + (iys + ly + PADY)] = o;
        }
        return;
    }

    // ---- event block: per-event parameter precompute ----
    const int e = (blk - NTILES) * 256 + tid;
    if (e >= E) return;

    const float dx = *dxp;
    const float dy = *dyp;
    const float nxf = (float)nx;
    const float nyf = (float)ny;

    const float p1x = 0.5f * (x1l[e] + x1r[e]);
    const float p1y = 0.5f * (y1l[e] + y1r[e]);
    const float p2x = 0.5f * (x2l[e] + x2r[e]);
    const float p2y = 0.5f * (y2l[e] + y2r[e]);
    const float dvx = p2x - p1x;
    const float dvy = p2y - p1y;
    const float L   = sqrtf(dvx * dvx + dvy * dvy);

    const float sigma     = (*trp) * 0.3f / (2.0f * 2.3548200450309493f);
    const float inv_sigma = 1.0f / sigma;
    const float norm      = 0.3989422804014327f * inv_sigma;
    const float tc        = 0.5f * L + 0.5f * tof[e];
    const float step      = L * INV_NSAMP;

    const float dfx = dvx * INV_NSAMP / dx;
    const float dfy = dvy * INV_NSAMP / dy;
    const float fx0 = (p1x + dvx * (0.5f * INV_NSAMP)) / dx + 0.5f * nxf - 0.5f;
    const float fy0 = (p1y + dvy * (0.5f * INV_NSAMP)) / dy + 0.5f * nyf - 0.5f;
    const float dz  = step * inv_sigma;          // > 0 (L > 0)
    const float z0  = (step * 0.5f - tc) * inv_sigma;

    int i_lo = (int)floorf((-ZCUT - z0) / dz);
    int i_hi = (int)ceilf (( ZCUT - z0) / dz);
    if (i_lo < 0)         i_lo = 0;
    if (i_lo > NSAMP - 1) i_lo = NSAMP - 1;
    if (i_hi < 0)         i_hi = 0;
    if (i_hi > NSAMP - 1) i_hi = NSAMP - 1;

    const bool steep = fabsf(dvy) > fabsf(dvx);
    const float a0 = (steep ? fy0 : fx0) + (float)PADX;
    const float da = steep ? dfy : dfx;
    const float b0 = (steep ? fx0 : fy0) + (float)PADY;
    const float db = steep ? dfx : dfy;

    unsigned packed = (unsigned)i_lo | ((unsigned)i_hi << 8) |
                      (steep ? 0x80000000u : 0u);

    g_pA[e] = make_float4(a0, da, b0, db);
    g_pB[e] = make_float4(z0, dz, norm * step, __uint_as_float(packed));
}

__global__ void __launch_bounds__(128)
project_kernel(float* __restrict__ out, int E)
{
    const int g = blockIdx.x * blockDim.x + threadIdx.x;
    int       e = g >> 3;                 // event index
    const int h = g & 7;                  // sample phase
    const bool valid = (e < E);
    if (!valid) e = E - 1;

    const float4 pA = g_pA[e];            // a0, da, b0, db
    const float4 pB = g_pB[e];            // z0, dz, scale, packed

    const unsigned packed = __float_as_uint(pB.w);
    const int  i_lo  = (int)(packed & 0xffu);
    const int  i_hi  = (int)((packed >> 8) & 0xffu);
    const bool steep = (packed & 0x80000000u) != 0u;

    const h4* __restrict__ base = steep ? g_padhT : g_padh;

    const float kexp = -0.72134752044448f;     // -0.5 * log2(e)
    const float da = pA.y, db = pA.w;
    const float dz = pB.y;

    // Per-lane initial sample and incremental state (stride 8 in i).
    const int   i0  = i_lo + h;
    const float fi0 = (float)i0;
    const float u0 = fmaf(fi0, da, pA.x);
    const float v0 = fmaf(fi0, db, pA.z);
    const float zs = fmaf(fi0, dz, pB.x);
    const float kd = kexp * dz;
    float q   = (kexp * zs) * zs;
    float dq  = kd * fmaf(64.0f, dz, 16.0f * zs);   // kexp*(16*dz*zs + 64*dz^2)
    const float ddq = 128.0f * kd * dz;

    // (u,v) packed as f32x2; one packed add per iteration.
    unsigned long long uv, duv;
    asm("mov.b64 %0, {%1, %2};" : "=l"(uv)  : "f"(u0),        "f"(v0));
    asm("mov.b64 %0, {%1, %2};" : "=l"(duv) : "f"(8.0f * da), "f"(8.0f * db));

    const int n = (i_hi - i0 >= 0) ? ((i_hi - i0) >> 3) + 1 : 0;

    float acc = 0.0f;

    #pragma unroll 4
    for (int it = 0; it < n; ++it) {
        float u, v;
        asm("mov.b64 {%0, %1}, %2;" : "=f"(u), "=f"(v) : "l"(uv));

        const int iu = (int)u;            // u,v > 0: trunc == floor
        const int iv = (int)v;
        const float wu = u - (float)iu;
        const float wv = v - (float)iv;

        const h4 c = base[iv * PAD_W + iu];

        const __half2 wu2 = __floats2half2_rn(wu, wu);
        const __half2 l2  = __hfma2(wu2, __hsub2(c.hi, c.lo), c.lo);

        const float l0 = __low2float(l2);
        const float l1 = __high2float(l2);
        const float val = fmaf(wv, l1 - l0, l0);

        float w;
        asm("ex2.approx.ftz.f32 %0, %1;" : "=f"(w) : "f"(q));
        acc = fmaf(w, val, acc);

        asm("add.rn.f32x2 %0, %1, %2;" : "=l"(uv) : "l"(uv), "l"(duv));
        q += dq; dq += ddq;
    }

    acc += __shfl_xor_sync(0xffffffffu, acc, 1);
    acc += __shfl_xor_sync(0xffffffffu, acc, 2);
    acc += __shfl_xor_sync(0xffffffffu, acc, 4);

    if (valid && h == 0)
        out[e] = acc * pB.z;
}

extern "C" void kernel_launch(void* const* d_in, const int* in_sizes, int n_in,
                              void* d_out, int out_size)
{
    const float* image = (const float*)d_in[0];
    const float* tof   = (const float*)d_in[1];
    const float* x1l   = (const float*)d_in[2];
    const float* y1l   = (const float*)d_in[3];
    const float* x1r   = (const float*)d_in[4];
    const float* y1r   = (const float*)d_in[5];
    const float* x2l   = (const float*)d_in[6];
    const float* y2l   = (const float*)d_in[7];
    const float* x2r   = (const float*)d_in[8];
    const float* y2r   = (const float*)d_in[9];
    const float* trp   = (const float*)d_in[10];
    const float* dxp   = (const float*)d_in[11];
    const float* dyp   = (const float*)d_in[12];
    const int*   nxp   = (const int*)d_in[13];
    const int*   nyp   = (const int*)d_in[14];

    const int E = in_sizes[1];

    const int tile_blocks  = NTILE * NTILE;
    const int event_blocks = (E + 255) / 256;
    prep_kernel<<<tile_blocks + event_blocks, 256>>>(image, tof,
                                                     x1l, y1l, x1r, y1r,
                                                     x2l, y2l, x2r, y2r,
                                                     trp, dxp, dyp, nxp, nyp, E);

    const int threads = 128;
    const long long total = (long long)E * SPLIT;
    const int blocks = (int)((total + threads - 1) / threads);
    project_kernel<<<blocks, threads>>>((float*)d_out, E);
}